// round 13
// baseline (speedup 1.0000x reference)
#include <cuda_runtime.h>
#include <cuda_bf16.h>

#define NUM_AA 20
#define FEAT_DIM 16
#define LUT_SIZE (NUM_AA * NUM_AA)
#define NTRI 210                 // 20*21/2 upper-triangle entries (incl diag)
#define NCOPIES 16               // bank-grouped LUT replicas (2 lanes per copy)
#define LUT_WORDS 6400           // ceil(400/2)*32 = 200*32 words = 25.6 KB

// Replicated-LUT addressing: entry k of copy c lives at word
//   ((k>>1)<<5) + (c<<1) + (k&1)   -> bank = 2c + (k&1), i.e. banks [2c, 2c+2).
// Lane l uses copy l>>1, so lane groups touch disjoint bank pairs and the
// warp-wide conflict degree is at most 2 (vs E~3.4 for a single copy).
__device__ __forceinline__ int lut_ofs(int k, int lbase) {
    return ((k & ~1) << 4) + lbase + (k & 1);
}

__global__ void __launch_bounds__(256, 7)
snack_fused(const float* __restrict__ features,
            const float* __restrict__ M,
            const int4*  __restrict__ ii4,
            const int4*  __restrict__ jj4,
            float4*      __restrict__ out4,
            int n4)
{
    __shared__ float sF [NUM_AA * FEAT_DIM];    // 320
    __shared__ float sM [FEAT_DIM * FEAT_DIM];  // 256
    __shared__ float sFM[NUM_AA * FEAT_DIM];    // 320
    __shared__ float s_lut[LUT_WORDS];          // 25.6 KB, 16 copies

    const int tid   = threadIdx.x;
    const int lbase = tid & 30;                 // (lane>>1)<<1

    // ---- Early-issue the first gather loads; they fly during the prologue ----
    const int stride = gridDim.x * blockDim.x;
    int t0 = blockIdx.x * blockDim.x + tid;
    int4 pa, pb;
    bool pv = t0 < n4;
    if (pv) { pa = ii4[t0]; pb = jj4[t0]; }

    // ---- Stage F and M ----
    sF[tid] = features[tid];
    if (tid < 64) sF[256 + tid] = features[256 + tid];
    sM[tid] = M[tid];
    __syncthreads();

    // ---- FM = F @ M  (320 entries, 16 FMA each) ----
    for (int k = tid; k < NUM_AA * FEAT_DIM; k += 256) {
        const int i = k >> 4, e = k & 15;
        float acc = 0.0f;
#pragma unroll
        for (int d = 0; d < FEAT_DIM; d++)
            acc = fmaf(sF[i * FEAT_DIM + d], sM[d * FEAT_DIM + e], acc);
        sFM[k] = acc;
    }
    __syncthreads();

    // ---- Symmetric LUT: 210 upper-triangle entries, one per thread,
    //      broadcast into all 16 bank-grouped copies ----
    if (tid < NTRI) {
        int i = 0, rem = tid;
#pragma unroll
        for (int r = 0; r < NUM_AA - 1; r++) {
            if (i == r && rem >= NUM_AA - r) { rem -= NUM_AA - r; i = r + 1; }
        }
        const int j = i + rem;

        const float4* F4  = (const float4*)sF;
        const float4* FM4 = (const float4*)sFM;
        float acc = 0.0f;
#pragma unroll
        for (int q = 0; q < 4; q++) {
            float4 fi = F4 [i * 4 + q], fj = F4 [j * 4 + q];
            float4 mi = FM4[i * 4 + q], mj = FM4[j * 4 + q];
            acc = fmaf(mi.x - mj.x, fi.x - fj.x, acc);
            acc = fmaf(mi.y - mj.y, fi.y - fj.y, acc);
            acc = fmaf(mi.z - mj.z, fi.z - fj.z, acc);
            acc = fmaf(mi.w - mj.w, fi.w - fj.w, acc);
        }
        const float v  = tanhf(acc);
        const int  k1  = i * NUM_AA + j;
        const int  k2  = j * NUM_AA + i;
#pragma unroll
        for (int c = 0; c < NCOPIES; c++) {
            s_lut[lut_ofs(k1, c << 1)] = v;
            s_lut[lut_ofs(k2, c << 1)] = v;
        }
    }
    __syncthreads();

    // ---- Gather: grid-stride, one float4 per iteration, preloaded head ----
    int t = t0;
    while (pv) {
        const int tn = t + stride;
        const bool vn = tn < n4;
        int4 an, bn;
        if (vn) { an = ii4[tn]; bn = jj4[tn]; }   // prefetch next iteration

        float4 o;
        o.x = s_lut[lut_ofs(pa.x * NUM_AA + pb.x, lbase)];
        o.y = s_lut[lut_ofs(pa.y * NUM_AA + pb.y, lbase)];
        o.z = s_lut[lut_ofs(pa.z * NUM_AA + pb.z, lbase)];
        o.w = s_lut[lut_ofs(pa.w * NUM_AA + pb.w, lbase)];
        out4[t] = o;

        t = tn; pa = an; pb = bn; pv = vn;
    }
}

// ---------------------------------------------------------------------------
// Tail: direct per-element compute (only if n % 4 != 0; never for n = 2^23).
// ---------------------------------------------------------------------------
__global__ void snack_tail(const float* __restrict__ features,
                           const float* __restrict__ M,
                           const int* __restrict__ ii,
                           const int* __restrict__ jj,
                           float* __restrict__ out,
                           int start, int n)
{
    int t = start + blockIdx.x * blockDim.x + threadIdx.x;
    if (t >= n) return;
    int i = ii[t], j = jj[t];
    float delta[FEAT_DIM];
#pragma unroll
    for (int d = 0; d < FEAT_DIM; d++)
        delta[d] = features[i * FEAT_DIM + d] - features[j * FEAT_DIM + d];
    float dist = 0.0f;
#pragma unroll
    for (int d = 0; d < FEAT_DIM; d++) {
        float md = 0.0f;
#pragma unroll
        for (int e = 0; e < FEAT_DIM; e++)
            md = fmaf(M[d * FEAT_DIM + e], delta[e], md);
        dist = fmaf(delta[d], md, dist);
    }
    out[t] = tanhf(dist);
}

extern "C" void kernel_launch(void* const* d_in, const int* in_sizes, int n_in,
                              void* d_out, int out_size) {
    const float* features = (const float*)d_in[0];
    const float* M        = (const float*)d_in[1];
    const int*   idx_i    = (const int*)d_in[2];
    const int*   idx_j    = (const int*)d_in[3];
    float*       out      = (float*)d_out;

    int n  = in_sizes[2];
    int n4 = n / 4;

    if (n4 > 0) {
        int blocks = 148 * 7;                 // one CTA generation at 7 CTAs/SM
        int needed = (n4 + 255) / 256;
        if (blocks > needed) blocks = needed;
        snack_fused<<<blocks, 256>>>(features, M,
                                     (const int4*)idx_i, (const int4*)idx_j,
                                     (float4*)out, n4);
    }

    int done = n4 * 4;
    int rem  = n - done;
    if (rem > 0) {
        snack_tail<<<(rem + 255) / 256, 256>>>(features, M, idx_i, idx_j,
                                               out, done, n);
    }
}

// round 15
// speedup vs baseline: 1.5783x; 1.5783x over previous
#include <cuda_runtime.h>
#include <cuda_bf16.h>

#define NUM_AA 20
#define FEAT_DIM 16
#define LUT_SIZE (NUM_AA * NUM_AA)
#define NTRI 210                  // 20*21/2 upper-triangle entries (incl diag)
// 8 replicated copies, 4 lanes per copy. Entry k of copy c lives at word
//   ((k>>2)<<5) + (c<<2) + (k&3)  -> bank = 4c + (k&3), i.e. banks [4c,4c+4).
// 100 rows of 32 words = 3200 words = 12.8 KB.
#define LUT_ROWS 100
#define LUT_WORDS (LUT_ROWS * 32)

__device__ __forceinline__ int lut_ofs(int k, int lgrp) {
    // bits: [(k>>2)<<5] | [lgrp in bits 2..4] | [k&3 in bits 0..1] (disjoint)
    return ((k & ~3) << 3) | lgrp | (k & 3);
}

__global__ void __launch_bounds__(256, 8)
snack_fused(const float* __restrict__ features,
            const float* __restrict__ M,
            const int4*  __restrict__ ii4,
            const int4*  __restrict__ jj4,
            float4*      __restrict__ out4,
            int n4)
{
    __shared__ float sF [NUM_AA * FEAT_DIM];    // 320
    __shared__ float sM [FEAT_DIM * FEAT_DIM];  // 256
    __shared__ float sFM[NUM_AA * FEAT_DIM];    // 320
    __shared__ float s_stage[LUT_SIZE];         // 400  (un-replicated LUT)
    __shared__ float s_lut[LUT_WORDS];          // 3200 (8 bank-grouped copies)

    const int tid  = threadIdx.x;
    const int lgrp = tid & 28;                  // (lane>>2)<<2, bits 2..4

    // ---- Stage F and M ----
    sF[tid] = features[tid];
    if (tid < 64) sF[256 + tid] = features[256 + tid];
    sM[tid] = M[tid];
    __syncthreads();

    // ---- FM = F @ M  (320 entries, 16 FMA each) ----
    for (int k = tid; k < NUM_AA * FEAT_DIM; k += 256) {
        const int i = k >> 4, e = k & 15;
        float acc = 0.0f;
#pragma unroll
        for (int d = 0; d < FEAT_DIM; d++)
            acc = fmaf(sF[i * FEAT_DIM + d], sM[d * FEAT_DIM + e], acc);
        sFM[k] = acc;
    }
    __syncthreads();

    // ---- Symmetric LUT into staging: 210 entries, one per thread ----
    if (tid < NTRI) {
        int i = 0, rem = tid;
#pragma unroll
        for (int r = 0; r < NUM_AA - 1; r++) {
            if (i == r && rem >= NUM_AA - r) { rem -= NUM_AA - r; i = r + 1; }
        }
        const int j = i + rem;

        const float4* F4  = (const float4*)sF;
        const float4* FM4 = (const float4*)sFM;
        float acc = 0.0f;
#pragma unroll
        for (int q = 0; q < 4; q++) {
            float4 fi = F4 [i * 4 + q], fj = F4 [j * 4 + q];
            float4 mi = FM4[i * 4 + q], mj = FM4[j * 4 + q];
            acc = fmaf(mi.x - mj.x, fi.x - fj.x, acc);
            acc = fmaf(mi.y - mj.y, fi.y - fj.y, acc);
            acc = fmaf(mi.z - mj.z, fi.z - fj.z, acc);
            acc = fmaf(mi.w - mj.w, fi.w - fj.w, acc);
        }
        const float v = tanhf(acc);
        s_stage[i * NUM_AA + j] = v;
        s_stage[j * NUM_AA + i] = v;
    }
    __syncthreads();

    // ---- Conflict-free replication scatter: 3200 words, coalesced STS ----
    // word w: source entry k = ((w>>5)<<2) + (w&3). Consecutive tids write
    // consecutive words (distinct banks); reads hit <=4 distinct stage words
    // per warp (broadcast within each) -> conflict-free both ways.
    for (int w = tid; w < LUT_WORDS; w += 256) {
        const int k = ((w >> 5) << 2) + (w & 3);
        s_lut[w] = s_stage[k];
    }
    __syncthreads();

    // ---- Gather: R10 loop shape, bank-grouped lookups ----
    const int stride = gridDim.x * blockDim.x;
#pragma unroll 2
    for (int t = blockIdx.x * blockDim.x + tid; t < n4; t += stride) {
        const int4 a = ii4[t];
        const int4 b = jj4[t];
        float4 o;
        o.x = s_lut[lut_ofs(a.x * NUM_AA + b.x, lgrp)];
        o.y = s_lut[lut_ofs(a.y * NUM_AA + b.y, lgrp)];
        o.z = s_lut[lut_ofs(a.z * NUM_AA + b.z, lgrp)];
        o.w = s_lut[lut_ofs(a.w * NUM_AA + b.w, lgrp)];
        out4[t] = o;
    }
}

// ---------------------------------------------------------------------------
// Tail: direct per-element compute (only if n % 4 != 0; never for n = 2^23).
// ---------------------------------------------------------------------------
__global__ void snack_tail(const float* __restrict__ features,
                           const float* __restrict__ M,
                           const int* __restrict__ ii,
                           const int* __restrict__ jj,
                           float* __restrict__ out,
                           int start, int n)
{
    int t = start + blockIdx.x * blockDim.x + threadIdx.x;
    if (t >= n) return;
    int i = ii[t], j = jj[t];
    float delta[FEAT_DIM];
#pragma unroll
    for (int d = 0; d < FEAT_DIM; d++)
        delta[d] = features[i * FEAT_DIM + d] - features[j * FEAT_DIM + d];
    float dist = 0.0f;
#pragma unroll
    for (int d = 0; d < FEAT_DIM; d++) {
        float md = 0.0f;
#pragma unroll
        for (int e = 0; e < FEAT_DIM; e++)
            md = fmaf(M[d * FEAT_DIM + e], delta[e], md);
        dist = fmaf(delta[d], md, dist);
    }
    out[t] = tanhf(dist);
}

extern "C" void kernel_launch(void* const* d_in, const int* in_sizes, int n_in,
                              void* d_out, int out_size) {
    const float* features = (const float*)d_in[0];
    const float* M        = (const float*)d_in[1];
    const int*   idx_i    = (const int*)d_in[2];
    const int*   idx_j    = (const int*)d_in[3];
    float*       out      = (float*)d_out;

    int n  = in_sizes[2];
    int n4 = n / 4;

    if (n4 > 0) {
        int blocks = 148 * 8;                 // one generation at 8 CTAs/SM
        int needed = (n4 + 255) / 256;
        if (blocks > needed) blocks = needed;
        snack_fused<<<blocks, 256>>>(features, M,
                                     (const int4*)idx_i, (const int4*)idx_j,
                                     (float4*)out, n4);
    }

    int done = n4 * 4;
    int rem  = n - done;
    if (rem > 0) {
        snack_tail<<<(rem + 255) / 256, 256>>>(features, M, idx_i, idx_j,
                                               out, done, n);
    }
}

// round 16
// speedup vs baseline: 1.7703x; 1.1216x over previous
#include <cuda_runtime.h>
#include <cuda_bf16.h>

#define NUM_AA 20
#define FEAT_DIM 16
#define LUT_SIZE (NUM_AA * NUM_AA)
#define NTRI 210                 // 20*21/2 upper-triangle entries (incl diag)

// ---------------------------------------------------------------------------
// Fused kernel (R10 prologue) + x2-chunk gather loop for doubled MLP.
// ---------------------------------------------------------------------------
__global__ void __launch_bounds__(256, 7)
snack_fused(const float* __restrict__ features,
            const float* __restrict__ M,
            const int4*  __restrict__ ii4,
            const int4*  __restrict__ jj4,
            float4*      __restrict__ out4,
            int n4)
{
    __shared__ float sF [NUM_AA * FEAT_DIM];    // 320
    __shared__ float sM [FEAT_DIM * FEAT_DIM];  // 256
    __shared__ float sFM[NUM_AA * FEAT_DIM];    // 320
    __shared__ float s_lut[LUT_SIZE];           // 400

    const int tid = threadIdx.x;

    // ---- Stage F and M ----
    sF[tid] = features[tid];
    if (tid < 64) sF[256 + tid] = features[256 + tid];
    sM[tid] = M[tid];
    __syncthreads();

    // ---- FM = F @ M  (320 entries, 16 FMA each) ----
    for (int k = tid; k < NUM_AA * FEAT_DIM; k += 256) {
        const int i = k >> 4, e = k & 15;
        float acc = 0.0f;
#pragma unroll
        for (int d = 0; d < FEAT_DIM; d++)
            acc = fmaf(sF[i * FEAT_DIM + d], sM[d * FEAT_DIM + e], acc);
        sFM[k] = acc;
    }
    __syncthreads();

    // ---- Symmetric LUT: 210 upper-triangle entries, one per thread ----
    if (tid < NTRI) {
        int i = 0, rem = tid;
#pragma unroll
        for (int r = 0; r < NUM_AA - 1; r++) {
            if (i == r && rem >= NUM_AA - r) { rem -= NUM_AA - r; i = r + 1; }
        }
        const int j = i + rem;

        const float4* F4  = (const float4*)sF;
        const float4* FM4 = (const float4*)sFM;
        float acc = 0.0f;
#pragma unroll
        for (int q = 0; q < 4; q++) {
            float4 fi = F4 [i * 4 + q], fj = F4 [j * 4 + q];
            float4 mi = FM4[i * 4 + q], mj = FM4[j * 4 + q];
            acc = fmaf(mi.x - mj.x, fi.x - fj.x, acc);
            acc = fmaf(mi.y - mj.y, fi.y - fj.y, acc);
            acc = fmaf(mi.z - mj.z, fi.z - fj.z, acc);
            acc = fmaf(mi.w - mj.w, fi.w - fj.w, acc);
        }
        const float v = tanhf(acc);
        s_lut[i * NUM_AA + j] = v;
        s_lut[j * NUM_AA + i] = v;
    }
    __syncthreads();

    // ---- Gather: two float4 chunks per iteration, loads batched first ----
    const int gstride = gridDim.x * blockDim.x;      // threads in grid
    const int step    = gstride * 2;                 // chunks per loop trip
    int t = blockIdx.x * blockDim.x + tid;

    // Main loop: both chunks valid.
    for (; t + gstride < n4; t += step) {
        const int t1 = t + gstride;
        const int4 a0 = ii4[t];
        const int4 b0 = jj4[t];
        const int4 a1 = ii4[t1];
        const int4 b1 = jj4[t1];

        float4 o0;
        o0.x = s_lut[a0.x * NUM_AA + b0.x];
        o0.y = s_lut[a0.y * NUM_AA + b0.y];
        o0.z = s_lut[a0.z * NUM_AA + b0.z];
        o0.w = s_lut[a0.w * NUM_AA + b0.w];
        out4[t] = o0;

        float4 o1;
        o1.x = s_lut[a1.x * NUM_AA + b1.x];
        o1.y = s_lut[a1.y * NUM_AA + b1.y];
        o1.z = s_lut[a1.z * NUM_AA + b1.z];
        o1.w = s_lut[a1.w * NUM_AA + b1.w];
        out4[t1] = o1;
    }
    // Remainder: at most one chunk left for this thread.
    if (t < n4) {
        const int4 a = ii4[t];
        const int4 b = jj4[t];
        float4 o;
        o.x = s_lut[a.x * NUM_AA + b.x];
        o.y = s_lut[a.y * NUM_AA + b.y];
        o.z = s_lut[a.z * NUM_AA + b.z];
        o.w = s_lut[a.w * NUM_AA + b.w];
        out4[t] = o;
    }
}

// ---------------------------------------------------------------------------
// Tail: direct per-element compute (only if n % 4 != 0; never for n = 2^23).
// ---------------------------------------------------------------------------
__global__ void snack_tail(const float* __restrict__ features,
                           const float* __restrict__ M,
                           const int* __restrict__ ii,
                           const int* __restrict__ jj,
                           float* __restrict__ out,
                           int start, int n)
{
    int t = start + blockIdx.x * blockDim.x + threadIdx.x;
    if (t >= n) return;
    int i = ii[t], j = jj[t];
    float delta[FEAT_DIM];
#pragma unroll
    for (int d = 0; d < FEAT_DIM; d++)
        delta[d] = features[i * FEAT_DIM + d] - features[j * FEAT_DIM + d];
    float dist = 0.0f;
#pragma unroll
    for (int d = 0; d < FEAT_DIM; d++) {
        float md = 0.0f;
#pragma unroll
        for (int e = 0; e < FEAT_DIM; e++)
            md = fmaf(M[d * FEAT_DIM + e], delta[e], md);
        dist = fmaf(delta[d], md, dist);
    }
    out[t] = tanhf(dist);
}

extern "C" void kernel_launch(void* const* d_in, const int* in_sizes, int n_in,
                              void* d_out, int out_size) {
    const float* features = (const float*)d_in[0];
    const float* M        = (const float*)d_in[1];
    const int*   idx_i    = (const int*)d_in[2];
    const int*   idx_j    = (const int*)d_in[3];
    float*       out      = (float*)d_out;

    int n  = in_sizes[2];
    int n4 = n / 4;

    if (n4 > 0) {
        int blocks = 148 * 7;                 // exactly one generation at 7/SM
        int needed = (n4 + 255) / 256;
        if (blocks > needed) blocks = needed;
        snack_fused<<<blocks, 256>>>(features, M,
                                     (const int4*)idx_i, (const int4*)idx_j,
                                     (float4*)out, n4);
    }

    int done = n4 * 4;
    int rem  = n - done;
    if (rem > 0) {
        snack_tail<<<(rem + 255) / 256, 256>>>(features, M, idx_i, idx_j,
                                               out, done, n);
    }
}